// round 13
// baseline (speedup 1.0000x reference)
#include <cuda_runtime.h>
#include <stdint.h>

#define NB 32
#define NC 512
#define T_IN 1024
#define T_OUT 4096

#define CPB 8                    // channels per CTA -> grid = 2048
#define NT  256                  // threads per CTA
#define EPT (T_IN / NT)          // durations per thread in the scan = 4
#define NW  (NT / 32)            // warps per CTA = 8

// ---------------------------------------------------------------------------
// Fused kernel: each CTA = (batch, 8-channel group).
//   Phase A: scan this batch's durations, scatter run-length index map to smem.
//   Phase B: gather enc rows through the smem map; 8 LDGs in flight per warp
//            before the paired streaming stores (write-once output).
// __launch_bounds__(NT, 8): cap regs at 32 so 8 CTAs fit per SM (occupancy is
// the binding resource — R12 showed reg pressure, not wave count, is what hurts).
// Durations may be int32 or int64 (JAX x64 ambiguity) — detected on-device:
// int64 LE => all odd 32-bit words of batch-0's row are zero (durations<=4096).
// ---------------------------------------------------------------------------
__global__ __launch_bounds__(NT, 8)
void length_regulate_kernel(const float* __restrict__ enc,
                            const int*   __restrict__ dur32,
                            float*       __restrict__ out) {
    const int groups_per_b = NC / CPB;              // 64
    const int b  = blockIdx.x / groups_per_b;
    const int cg = blockIdx.x % groups_per_b;
    const int tid = threadIdx.x;

    __shared__ int sidx[T_OUT];                     // 16 KB index map
    __shared__ int wsum[NW];                        // per-warp scan sums

    // ---- dtype detection: OR of odd words in first 2048 int32s ----
    int odd = 0;
#pragma unroll
    for (int i = 0; i < T_IN / NT; ++i)
        odd |= dur32[2 * (i * NT + tid) + 1];
    const bool is32 = __syncthreads_or(odd) != 0;

    // ---- Phase A: scan + scatter ----
    int d[EPT];
    {
        const int j0 = tid * EPT;
        if (is32) {
#pragma unroll
            for (int k = 0; k < EPT; ++k) d[k] = dur32[b * T_IN + j0 + k];
        } else {
#pragma unroll
            for (int k = 0; k < EPT; ++k) d[k] = dur32[(b * T_IN + j0 + k) * 2];
        }
    }
    int tot = 0;
    int pre[EPT];
#pragma unroll
    for (int k = 0; k < EPT; ++k) { pre[k] = tot; tot += d[k]; }

    const int lane = tid & 31;
    const int warp = tid >> 5;

    int incl = tot;
#pragma unroll
    for (int o = 1; o < 32; o <<= 1) {
        int n = __shfl_up_sync(0xffffffffu, incl, o);
        if (lane >= o) incl += n;
    }
    if (lane == 31) wsum[warp] = incl;
    __syncthreads();

    // all 32 lanes of warp 0 participate (partial-warp full-mask shfl hangs)
    if (warp == 0) {
        int w = (lane < NW) ? wsum[lane] : 0;
#pragma unroll
        for (int o = 1; o < 32; o <<= 1) {
            int n = __shfl_up_sync(0xffffffffu, w, o);
            if (lane >= o) w += n;
        }
        if (lane < NW) wsum[lane] = w;
    }
    __syncthreads();

    int base = (incl - tot) + (warp ? wsum[warp - 1] : 0);

    {
        const int j0 = tid * EPT;
#pragma unroll
        for (int k = 0; k < EPT; ++k) {
            const int s = base + pre[k];
            const int e = s + d[k];
            for (int t = s; t < e; ++t) sidx[t] = j0 + k;
        }
    }
    __syncthreads();

    // ---- Phase B: gather with 2-way ILP + streaming stores ----
    const int c0 = cg * CPB;
    const size_t rowbase = (size_t)(b * NC + c0);
    const int4* __restrict__ si4 = (const int4*)sidx;

#pragma unroll
    for (int cc = 0; cc < CPB; ++cc) {
        const float* __restrict__ erow = enc + (rowbase + cc) * T_IN;
        float4*      __restrict__ orow = (float4*)(out + (rowbase + cc) * T_OUT);

#pragma unroll
        for (int it = 0; it < (T_OUT / 4) / (2 * NT); ++it) {  // 2 iters
            const int ta = (2 * it) * NT + tid;
            const int tb = ta + NT;
            const int4 ia = si4[ta];
            const int4 ib = si4[tb];

            float4 oa, ob;                 // 8 loads in flight before stores
            oa.x = __ldg(erow + ia.x);
            oa.y = __ldg(erow + ia.y);
            oa.z = __ldg(erow + ia.z);
            oa.w = __ldg(erow + ia.w);
            ob.x = __ldg(erow + ib.x);
            ob.y = __ldg(erow + ib.y);
            ob.z = __ldg(erow + ib.z);
            ob.w = __ldg(erow + ib.w);

            __stcs(orow + ta, oa);
            __stcs(orow + tb, ob);
        }
    }
}

// ---------------------------------------------------------------------------
extern "C" void kernel_launch(void* const* d_in, const int* in_sizes, int n_in,
                              void* d_out, int out_size) {
    const void* enc_p = d_in[0];
    const void* dur_p = d_in[1];
    if (n_in >= 2 && in_sizes[0] == NB * T_IN) {    // durations came first
        dur_p = d_in[0];
        enc_p = d_in[1];
    }
    length_regulate_kernel<<<NB * (NC / CPB), NT>>>(
        (const float*)enc_p, (const int*)dur_p, (float*)d_out);
}